// round 1
// baseline (speedup 1.0000x reference)
#include <cuda_runtime.h>

// ============================================================================
// GUSC1 ISTA-net baseline (round 0): fp32 FFMA GEMMs, correctness-first.
//
// Structure per launch:
//   zero (s|z) and A@(s|z) buffers
//   t = A @ x_c                     (batched GEMM, 64 cols/batch)
//   bx = mlpB(t)                    (two small GEMMs with relu/bias epilogues)
//   8x iterations:
//     Asz = A @ (s|z)               (batched GEMM, 128 cols/batch; skipped it=0)
//     y   = mlpA(Asz[:, :64]) + bx
//     t   = A @ y
//     s'  = mlpD(t) + mlpE(Asz[:, 64:])
//     (s, z) = (s', soft_threshold(s'))   packed interleaved for next A-pass
//   out[0:R*64]    = mlpD(s)
//   out[R*64:2R*64]= s
// ============================================================================

namespace cfg {
constexpr int  BATCH = 4;
constexpr int  N     = 8192;
constexpr int  DIM   = 64;
constexpr int  HID   = 128;
constexpr int  ITERS = 8;
constexpr long ROWS  = (long)BATCH * N;   // 32768
}

// Scratch (device globals; no allocation allowed in kernel_launch)
__device__ float g_sz  [cfg::BATCH * cfg::N * 128];  // (s | z) interleaved, ld=128
__device__ float g_Asz [cfg::BATCH * cfg::N * 128];  // A@(s|z), ld=128
__device__ float g_t64 [cfg::BATCH * cfg::N * 64];   // A@x then A@y
__device__ float g_bx  [cfg::BATCH * cfg::N * 64];
__device__ float g_y   [cfg::BATCH * cfg::N * 64];
__device__ float g_hid [cfg::BATCH * cfg::N * 128];  // MLP hidden scratch
__device__ float g_snew[cfg::BATCH * cfg::N * 64];   // s before packing

// ----------------------------------------------------------------------------
// Generic fp32 GEMM: C[b] = A[b] @ B[b] with epilogue.
// BM=128, BN=64, BK=8, 256 threads, 8x4 per-thread microtile.
// epi: 0 = none, 1 = +bias then relu, 2 = +bias (+ optional addbuf)
// ----------------------------------------------------------------------------
__global__ __launch_bounds__(256) void sgemm64(
    const float* __restrict__ Am, int lda, long strideA,
    const float* __restrict__ Bm, int ldb, long strideB,
    float*       __restrict__ Cm, int ldc, long strideC,
    int K, int epi,
    const float* __restrict__ bias,
    const float* __restrict__ addbuf, int ldadd)
{
    constexpr int BM = 128, BN = 64, BK = 8, TM = 8, TN = 4;
    __shared__ float As[BK][BM + 4];
    __shared__ float Bs[BK][BN + 4];

    const int  bz    = blockIdx.z;
    const int  ncol0 = blockIdx.y * BN;
    const float* Ab = Am + (long)bz * strideA;
    const float* Bb = Bm + (long)bz * strideB + ncol0;
    float*       Cb = Cm + (long)bz * strideC + ncol0;

    const long m0  = (long)blockIdx.x * BM;
    const int  tid = threadIdx.x;
    const int  tx  = tid & 15;    // 16 col-groups of TN=4 -> 64 cols
    const int  ty  = tid >> 4;    // 16 row-groups of TM=8 -> 128 rows

    // cooperative tile-load mapping
    const int arow = tid >> 1;         // 0..127
    const int acol = (tid & 1) * 4;    // 0 or 4
    const int brow = tid >> 5;         // 0..7
    const int bcol = (tid & 31) * 2;   // 0..62

    float acc[TM][TN];
#pragma unroll
    for (int i = 0; i < TM; i++)
#pragma unroll
        for (int j = 0; j < TN; j++) acc[i][j] = 0.f;

    for (int k0 = 0; k0 < K; k0 += BK) {
        float4 av = *reinterpret_cast<const float4*>(Ab + (m0 + arow) * lda + k0 + acol);
        As[acol + 0][arow] = av.x;
        As[acol + 1][arow] = av.y;
        As[acol + 2][arow] = av.z;
        As[acol + 3][arow] = av.w;
        float2 bv = *reinterpret_cast<const float2*>(Bb + (long)(k0 + brow) * ldb + bcol);
        Bs[brow][bcol]     = bv.x;
        Bs[brow][bcol + 1] = bv.y;
        __syncthreads();
#pragma unroll
        for (int kk = 0; kk < BK; kk++) {
            float a[TM], b[TN];
#pragma unroll
            for (int i = 0; i < TM; i++) a[i] = As[kk][ty * TM + i];
#pragma unroll
            for (int j = 0; j < TN; j++) b[j] = Bs[kk][tx * TN + j];
#pragma unroll
            for (int i = 0; i < TM; i++)
#pragma unroll
                for (int j = 0; j < TN; j++)
                    acc[i][j] = fmaf(a[i], b[j], acc[i][j]);
        }
        __syncthreads();
    }

#pragma unroll
    for (int i = 0; i < TM; i++) {
        const long row = m0 + ty * TM + i;
#pragma unroll
        for (int j = 0; j < TN; j++) {
            const int col = tx * TN + j;
            float v = acc[i][j];
            if (epi >= 1) v += bias[ncol0 + col];
            if (epi == 1) v = fmaxf(v, 0.f);
            if (addbuf != nullptr) v += addbuf[row * ldadd + ncol0 + col];
            Cb[row * ldc + col] = v;
        }
    }
}

// zero both 128-wide scratch buffers (s|z and A@(s|z))
__global__ __launch_bounds__(256) void zero2_kernel()
{
    const long n = cfg::ROWS * 128;
    long idx = (long)blockIdx.x * blockDim.x + threadIdx.x;
    if (idx < n) {
        g_sz[idx]  = 0.f;
        g_Asz[idx] = 0.f;
    }
}

// pack s and z = soft_threshold(s, alpha) into interleaved (s|z) buffer
__global__ __launch_bounds__(256) void soft_pack_kernel(
    const float* __restrict__ s, const float* __restrict__ alphaPtr)
{
    const long n = cfg::ROWS * 64;
    long idx = (long)blockIdx.x * blockDim.x + threadIdx.x;
    if (idx >= n) return;
    const float a = alphaPtr[0];
    const long r = idx >> 6;
    const int  c = (int)(idx & 63);
    const float v = s[idx];
    const float z = (v > a) ? (v - a) : ((v < -a) ? (v + a) : 0.f);
    g_sz[r * 128 + c]      = v;
    g_sz[r * 128 + 64 + c] = z;
}

// copy final s out of the interleaved buffer into the output's second half
__global__ __launch_bounds__(256) void copy_s_kernel(float* __restrict__ out)
{
    const long n = cfg::ROWS * 64;
    long idx = (long)blockIdx.x * blockDim.x + threadIdx.x;
    if (idx >= n) return;
    out[idx] = g_sz[(idx >> 6) * 128 + (idx & 63)];
}

extern "C" void kernel_launch(void* const* d_in, const int* in_sizes, int n_in,
                              void* d_out, int out_size)
{
    using namespace cfg;
    const float* x_c   = (const float*)d_in[0];
    const float* A     = (const float*)d_in[1];
    const float* alpha = (const float*)d_in[2];
    const float* WA1 = (const float*)d_in[3];
    const float* bA1 = (const float*)d_in[4];
    const float* WA2 = (const float*)d_in[5];
    const float* bA2 = (const float*)d_in[6];
    const float* WB1 = (const float*)d_in[7];
    const float* bB1 = (const float*)d_in[8];
    const float* WB2 = (const float*)d_in[9];
    const float* bB2 = (const float*)d_in[10];
    const float* WD1 = (const float*)d_in[11];
    const float* bD1 = (const float*)d_in[12];
    const float* WD2 = (const float*)d_in[13];
    const float* bD2 = (const float*)d_in[14];
    const float* WE1 = (const float*)d_in[15];
    const float* bE1 = (const float*)d_in[16];
    const float* WE2 = (const float*)d_in[17];
    const float* bE2 = (const float*)d_in[18];
    float* out = (float*)d_out;

    float *sz, *Asz, *t64, *bxp, *yp, *hid, *snew;
    cudaGetSymbolAddress((void**)&sz,   g_sz);
    cudaGetSymbolAddress((void**)&Asz,  g_Asz);
    cudaGetSymbolAddress((void**)&t64,  g_t64);
    cudaGetSymbolAddress((void**)&bxp,  g_bx);
    cudaGetSymbolAddress((void**)&yp,   g_y);
    cudaGetSymbolAddress((void**)&hid,  g_hid);
    cudaGetSymbolAddress((void**)&snew, g_snew);

    const long bsX64  = (long)N * 64;
    const long bsX128 = (long)N * 128;

    const dim3 blk(256);
    const dim3 gA64 (N / 128, 1, BATCH);   // A @ [N,64]  per batch
    const dim3 gA128(N / 128, 2, BATCH);   // A @ [N,128] per batch
    const dim3 gM128((int)(ROWS / 128), 2, 1);  // MLP layer 1: [R,64/128]@[.,128]
    const dim3 gM64 ((int)(ROWS / 128), 1, 1);  // MLP layer 2: [R,128]@[.,64]

    // --- init scratch: s = z = 0, A@(s|z) = 0 (so it=0 skips the big GEMM) ---
    {
        long n = ROWS * 128;
        zero2_kernel<<<(unsigned)((n + 255) / 256), blk>>>();
    }

    // --- t64 = A @ x_c (batched) ---
    sgemm64<<<gA64, blk>>>(A, N, 0, x_c, 64, bsX64, t64, 64, bsX64,
                           N, 0, nullptr, nullptr, 0);
    // --- bx = mlpB(t64) ---
    sgemm64<<<gM128, blk>>>(t64, 64, 0, WB1, HID, 0, hid, HID, 0,
                            DIM, 1, bB1, nullptr, 0);
    sgemm64<<<gM64, blk>>>(hid, HID, 0, WB2, 64, 0, bxp, 64, 0,
                           HID, 2, bB2, nullptr, 0);

    for (int it = 0; it < ITERS; it++) {
        // Asz = A @ (s|z)   (skip at it=0: buffers are zero)
        if (it > 0) {
            sgemm64<<<gA128, blk>>>(A, N, 0, sz, 128, bsX128, Asz, 128, bsX128,
                                    N, 0, nullptr, nullptr, 0);
        }
        // y = mlpA(Asz[:, 0:64]) + bx
        sgemm64<<<gM128, blk>>>(Asz, 128, 0, WA1, HID, 0, hid, HID, 0,
                                DIM, 1, bA1, nullptr, 0);
        sgemm64<<<gM64, blk>>>(hid, HID, 0, WA2, 64, 0, yp, 64, 0,
                               HID, 2, bA2, bxp, 64);
        // t64 = A @ y (batched)
        sgemm64<<<gA64, blk>>>(A, N, 0, yp, 64, bsX64, t64, 64, bsX64,
                               N, 0, nullptr, nullptr, 0);
        // snew = mlpD(t64)
        sgemm64<<<gM128, blk>>>(t64, 64, 0, WD1, HID, 0, hid, HID, 0,
                                DIM, 1, bD1, nullptr, 0);
        sgemm64<<<gM64, blk>>>(hid, HID, 0, WD2, 64, 0, snew, 64, 0,
                               HID, 2, bD2, nullptr, 0);
        // snew += mlpE(Asz[:, 64:128])
        sgemm64<<<gM128, blk>>>(Asz + 64, 128, 0, WE1, HID, 0, hid, HID, 0,
                                DIM, 1, bE1, nullptr, 0);
        sgemm64<<<gM64, blk>>>(hid, HID, 0, WE2, 64, 0, snew, 64, 0,
                               HID, 2, bE2, snew, 64);
        // (s, z=soft_threshold(s)) -> interleaved sz
        {
            long n = ROWS * 64;
            soft_pack_kernel<<<(unsigned)((n + 255) / 256), blk>>>(snew, alpha);
        }
    }

    // --- out[:R*64] = mlpD(s) ; out[R*64:] = s ---
    sgemm64<<<gM128, blk>>>(sz, 128, 0, WD1, HID, 0, hid, HID, 0,
                            DIM, 1, bD1, nullptr, 0);
    sgemm64<<<gM64, blk>>>(hid, HID, 0, WD2, 64, 0, out, 64, 0,
                           HID, 2, bD2, nullptr, 0);
    {
        long n = ROWS * 64;
        copy_s_kernel<<<(unsigned)((n + 255) / 256), blk>>>(out + ROWS * 64);
    }
}

// round 4
// speedup vs baseline: 3.4746x; 3.4746x over previous
#include <cuda_runtime.h>
#include <cuda_bf16.h>
#include <cstdint>

// ============================================================================
// GUSC1 ISTA-net round 4: big A-GEMMs on mma.sync (HMMA bf16, split-bf16 for
// fp32 accuracy). Fixed R3 compile error (removed dead lambda).
// ============================================================================

namespace cfg {
constexpr int  BATCH = 4;
constexpr int  N     = 8192;
constexpr int  DIM   = 64;
constexpr int  HID   = 128;
constexpr int  ITERS = 8;
constexpr long ROWS  = (long)BATCH * N;   // 32768
}

// ---------------------------------------------------------------------------
// Scratch (device globals)
// ---------------------------------------------------------------------------
__device__ float g_sz  [cfg::BATCH * cfg::N * 128];
__device__ float g_Asz [cfg::BATCH * cfg::N * 128];
__device__ float g_t64 [cfg::BATCH * cfg::N * 64];
__device__ float g_bx  [cfg::BATCH * cfg::N * 64];
__device__ float g_y   [cfg::BATCH * cfg::N * 64];
__device__ float g_hid [cfg::BATCH * cfg::N * 128];
__device__ float g_snew[cfg::BATCH * cfg::N * 64];

__device__ __nv_bfloat16 g_Ahi[(long)cfg::N * cfg::N];
__device__ __nv_bfloat16 g_Alo[(long)cfg::N * cfg::N];
__device__ __nv_bfloat16 g_Xhi[512L * cfg::N];   // [col, K] K-major
__device__ __nv_bfloat16 g_Xlo[512L * cfg::N];

// ---------------------------------------------------------------------------
// helpers
// ---------------------------------------------------------------------------
__device__ __forceinline__ uint32_t smem_to_u32(const void* p) {
    uint32_t a;
    asm("{ .reg .u64 t; cvta.to.shared.u64 t, %1; cvt.u32.u64 %0, t; }"
        : "=r"(a) : "l"(p));
    return a;
}
__device__ __forceinline__ void cp_async16(uint32_t dst, const void* src) {
    asm volatile("cp.async.cg.shared.global [%0], [%1], 16;" :: "r"(dst), "l"(src));
}
__device__ __forceinline__ void cp_async_commit() {
    asm volatile("cp.async.commit_group;");
}
template <int NWAIT>
__device__ __forceinline__ void cp_async_wait() {
    asm volatile("cp.async.wait_group %0;" :: "n"(NWAIT));
}
__device__ __forceinline__ void ldsm_x4(uint32_t& r0, uint32_t& r1,
                                        uint32_t& r2, uint32_t& r3, uint32_t addr) {
    asm volatile("ldmatrix.sync.aligned.m8n8.x4.shared.b16 {%0,%1,%2,%3}, [%4];"
                 : "=r"(r0), "=r"(r1), "=r"(r2), "=r"(r3) : "r"(addr));
}
__device__ __forceinline__ void mma16816(float& c0, float& c1, float& c2, float& c3,
                                         uint32_t a0, uint32_t a1, uint32_t a2, uint32_t a3,
                                         uint32_t b0, uint32_t b1) {
    asm volatile("mma.sync.aligned.m16n8k16.row.col.f32.bf16.bf16.f32 "
                 "{%0,%1,%2,%3}, {%4,%5,%6,%7}, {%8,%9}, {%0,%1,%2,%3};"
                 : "+f"(c0), "+f"(c1), "+f"(c2), "+f"(c3)
                 : "r"(a0), "r"(a1), "r"(a2), "r"(a3), "r"(b0), "r"(b1));
}

// ---------------------------------------------------------------------------
// HMMA split-bf16 GEMM: out = A_fp32 @ X_fp32 (both as hi+lo bf16, 3 terms)
// A: [8192, 8192] row-major K-major; Xt: [cols, 8192] K-major.
// BM=128, BN=128, KT=64, 512 threads, 16 warps (4x4), warp tile 32x32.
// Output col g -> out[((g>>cbShift)*8192 + row) * CB + (g & (CB-1))].
// ---------------------------------------------------------------------------
namespace tg {
constexpr int K   = 8192;
constexpr int KT  = 64;
constexpr int NCH = K / KT;          // 128
constexpr int BM  = 128;
constexpr int BN  = 128;
constexpr uint32_t SZ_T = 128 * 128; // 16384 B per (128-row x 128B) tile
constexpr uint32_t STG  = 4 * SZ_T;  // Ah, Al, Bh, Bl = 65536 B
constexpr uint32_t SMEM_TOTAL = 2 * STG;   // 131072
}

// swizzled byte offset within a [row][128B] tile
__device__ __forceinline__ uint32_t swz(int row, int x) {
    return (uint32_t)(row * 128 + (x ^ ((row & 7) << 4)));
}

__global__ __launch_bounds__(512) void tgemm_hmma(
    const __nv_bfloat16* __restrict__ Ahi, const __nv_bfloat16* __restrict__ Alo,
    const __nv_bfloat16* __restrict__ Bhi, const __nv_bfloat16* __restrict__ Blo,
    float* __restrict__ out, int cbShift)
{
    using namespace tg;
    extern __shared__ char smem[];
    const uint32_t sb  = smem_to_u32(smem);
    const int tid  = threadIdx.x;
    const int lane = tid & 31;
    const int wid  = tid >> 5;
    const int wm   = wid >> 2;      // 0..3
    const int wn   = wid & 3;       // 0..3
    const long m0  = (long)blockIdx.x * BM;
    const int  n0  = blockIdx.y * BN;

    // stage loader geometry: 4 tiles/stage, each 1024 x 16B chunks;
    // 512 threads -> 2 chunks per tile per thread.
    const int c0r = tid >> 3;          // rows 0..63
    const int c0s = tid & 7;
    const int c1r = c0r + 64;          // rows 64..127

    float acc[2][4][4];
#pragma unroll
    for (int i = 0; i < 2; i++)
#pragma unroll
        for (int j = 0; j < 4; j++)
#pragma unroll
            for (int q = 0; q < 4; q++) acc[i][j][q] = 0.f;

    // ldmatrix per-lane geometry (within 128B-row tiles)
    const int q    = lane >> 3;        // 0..3
    const int r8   = lane & 7;
    // A frag (m16 x k16): rows a_row_off + mi*16, k-bytes kb + a_k_off
    const int a_row_off = wm * 32 + r8 + (q & 1) * 8;
    const int a_k_off   = (q >> 1) * 16;
    // B frag (n16 x k16)
    const int b_row_off = wn * 32 + r8 + (q >> 1) * 8;
    const int b_k_off   = (q & 1) * 16;

#define LOAD_STAGE(ST, K0)                                                     \
    do {                                                                       \
        const uint32_t base_ = sb + (uint32_t)(ST) * STG;                      \
        const uint32_t o0_ = swz(c0r, c0s * 16);                               \
        const uint32_t o1_ = swz(c1r, c0s * 16);                               \
        const long ga0_ = (m0 + c0r) * (long)K + (K0) + c0s * 8;               \
        const long ga1_ = (m0 + c1r) * (long)K + (K0) + c0s * 8;               \
        const long gb0_ = ((long)n0 + c0r) * K + (K0) + c0s * 8;               \
        const long gb1_ = ((long)n0 + c1r) * K + (K0) + c0s * 8;               \
        cp_async16(base_ + o0_,              Ahi + ga0_);                      \
        cp_async16(base_ + o1_,              Ahi + ga1_);                      \
        cp_async16(base_ + SZ_T + o0_,       Alo + ga0_);                      \
        cp_async16(base_ + SZ_T + o1_,       Alo + ga1_);                      \
        cp_async16(base_ + 2 * SZ_T + o0_,   Bhi + gb0_);                      \
        cp_async16(base_ + 2 * SZ_T + o1_,   Bhi + gb1_);                      \
        cp_async16(base_ + 3 * SZ_T + o0_,   Blo + gb0_);                      \
        cp_async16(base_ + 3 * SZ_T + o1_,   Blo + gb1_);                      \
        cp_async_commit();                                                     \
    } while (0)

    LOAD_STAGE(0, 0);

    for (int i = 0; i < NCH; i++) {
        if (i + 1 < NCH) {
            LOAD_STAGE((i + 1) & 1, (i + 1) * KT);
            cp_async_wait<1>();
        } else {
            cp_async_wait<0>();
        }
        __syncthreads();

        const uint32_t base = sb + (uint32_t)(i & 1) * STG;
        const uint32_t aHB = base;
        const uint32_t aLB = base + SZ_T;
        const uint32_t bHB = base + 2 * SZ_T;
        const uint32_t bLB = base + 3 * SZ_T;

#pragma unroll
        for (int s = 0; s < 4; s++) {
            const int kb = s * 32;
            uint32_t ah[2][4], al[2][4], bh[2][4], bl[2][4];
#pragma unroll
            for (int mi = 0; mi < 2; mi++) {
                const uint32_t ad = swz(a_row_off + mi * 16, kb + a_k_off);
                ldsm_x4(ah[mi][0], ah[mi][1], ah[mi][2], ah[mi][3], aHB + ad);
                ldsm_x4(al[mi][0], al[mi][1], al[mi][2], al[mi][3], aLB + ad);
            }
#pragma unroll
            for (int ni = 0; ni < 2; ni++) {
                const uint32_t bd = swz(b_row_off + ni * 16, kb + b_k_off);
                ldsm_x4(bh[ni][0], bh[ni][1], bh[ni][2], bh[ni][3], bHB + bd);
                ldsm_x4(bl[ni][0], bl[ni][1], bl[ni][2], bl[ni][3], bLB + bd);
            }
#pragma unroll
            for (int mi = 0; mi < 2; mi++) {
#pragma unroll
                for (int nj = 0; nj < 4; nj++) {
                    const int g = nj >> 1, h = (nj & 1) * 2;
                    float* c = acc[mi][nj];
                    mma16816(c[0], c[1], c[2], c[3],
                             ah[mi][0], ah[mi][1], ah[mi][2], ah[mi][3],
                             bh[g][h], bh[g][h + 1]);
                    mma16816(c[0], c[1], c[2], c[3],
                             al[mi][0], al[mi][1], al[mi][2], al[mi][3],
                             bh[g][h], bh[g][h + 1]);
                    mma16816(c[0], c[1], c[2], c[3],
                             ah[mi][0], ah[mi][1], ah[mi][2], ah[mi][3],
                             bl[g][h], bl[g][h + 1]);
                }
            }
        }
        __syncthreads();
    }

    // ---- epilogue ----
    const int CB = 1 << cbShift;
    const int cbMask = CB - 1;
#pragma unroll
    for (int mi = 0; mi < 2; mi++) {
        const long row = m0 + wm * 32 + mi * 16 + (lane >> 2);
#pragma unroll
        for (int nj = 0; nj < 4; nj++) {
            const int g = n0 + wn * 32 + nj * 8 + 2 * (lane & 3);
            const int b = g >> cbShift;
            const int c = g & cbMask;
            float* p0 = out + ((long)b * 8192 + row) * CB + c;
            float* p1 = out + ((long)b * 8192 + row + 8) * CB + c;
            *reinterpret_cast<float2*>(p0) = make_float2(acc[mi][nj][0], acc[mi][nj][1]);
            *reinterpret_cast<float2*>(p1) = make_float2(acc[mi][nj][2], acc[mi][nj][3]);
        }
    }
#undef LOAD_STAGE
}

// ---------------------------------------------------------------------------
// A split: Ahi = bf16(a); Alo = bf16(a - Ahi)
// ---------------------------------------------------------------------------
__global__ __launch_bounds__(256) void split_A_kernel(const float* __restrict__ A)
{
    const long n = (long)cfg::N * cfg::N;
    long idx = ((long)blockIdx.x * blockDim.x + threadIdx.x) * 4;
    if (idx >= n) return;
    float4 v = *reinterpret_cast<const float4*>(A + idx);
    float f[4] = {v.x, v.y, v.z, v.w};
#pragma unroll
    for (int q = 0; q < 4; q++) {
        __nv_bfloat16 hi = __float2bfloat16(f[q]);
        g_Ahi[idx + q] = hi;
        g_Alo[idx + q] = __float2bfloat16(f[q] - __bfloat162float(hi));
    }
}

// ---------------------------------------------------------------------------
// Split + transpose X: [B*N, CB] fp32 -> Xt hi/lo [B*CB, K] bf16
// ---------------------------------------------------------------------------
__global__ __launch_bounds__(256) void split_transpose_kernel(
    const float* __restrict__ X, int CB)
{
    __shared__ float tile[32][33];
    const int k0 = blockIdx.x * 32;
    const int j0 = blockIdx.y * 32;
    const int b  = j0 / CB;
    const int c0 = j0 % CB;
    const int tx = threadIdx.x, ty = threadIdx.y;

    for (int r = ty; r < 32; r += 8)
        tile[r][tx] = X[((long)b * cfg::N + k0 + r) * CB + c0 + tx];
    __syncthreads();
    for (int r = ty; r < 32; r += 8) {
        const float v = tile[tx][r];
        const __nv_bfloat16 hi = __float2bfloat16(v);
        const long o = (long)(j0 + r) * cfg::N + k0 + tx;
        g_Xhi[o] = hi;
        g_Xlo[o] = __float2bfloat16(v - __bfloat162float(hi));
    }
}

// ----------------------------------------------------------------------------
// fp32 FFMA GEMM for the small MLPs (unchanged; proven in R1)
// ----------------------------------------------------------------------------
__global__ __launch_bounds__(256) void sgemm64(
    const float* __restrict__ Am, int lda, long strideA,
    const float* __restrict__ Bm, int ldb, long strideB,
    float*       __restrict__ Cm, int ldc, long strideC,
    int K, int epi,
    const float* __restrict__ bias,
    const float* __restrict__ addbuf, int ldadd)
{
    constexpr int BM = 128, BN = 64, BK = 8, TM = 8, TN = 4;
    __shared__ float As[BK][BM + 4];
    __shared__ float Bs[BK][BN + 4];

    const int  bz    = blockIdx.z;
    const int  ncol0 = blockIdx.y * BN;
    const float* Ab = Am + (long)bz * strideA;
    const float* Bb = Bm + (long)bz * strideB + ncol0;
    float*       Cb = Cm + (long)bz * strideC + ncol0;

    const long m0  = (long)blockIdx.x * BM;
    const int  tid = threadIdx.x;
    const int  tx  = tid & 15;
    const int  ty  = tid >> 4;

    const int arow = tid >> 1;
    const int acol = (tid & 1) * 4;
    const int brow = tid >> 5;
    const int bcol = (tid & 31) * 2;

    float acc[TM][TN];
#pragma unroll
    for (int i = 0; i < TM; i++)
#pragma unroll
        for (int j = 0; j < TN; j++) acc[i][j] = 0.f;

    for (int k0 = 0; k0 < K; k0 += BK) {
        float4 av = *reinterpret_cast<const float4*>(Ab + (m0 + arow) * lda + k0 + acol);
        As[acol + 0][arow] = av.x;
        As[acol + 1][arow] = av.y;
        As[acol + 2][arow] = av.z;
        As[acol + 3][arow] = av.w;
        float2 bv = *reinterpret_cast<const float2*>(Bb + (long)(k0 + brow) * ldb + bcol);
        Bs[brow][bcol]     = bv.x;
        Bs[brow][bcol + 1] = bv.y;
        __syncthreads();
#pragma unroll
        for (int kk = 0; kk < BK; kk++) {
            float a[TM], b[TN];
#pragma unroll
            for (int i = 0; i < TM; i++) a[i] = As[kk][ty * TM + i];
#pragma unroll
            for (int j = 0; j < TN; j++) b[j] = Bs[kk][tx * TN + j];
#pragma unroll
            for (int i = 0; i < TM; i++)
#pragma unroll
                for (int j = 0; j < TN; j++)
                    acc[i][j] = fmaf(a[i], b[j], acc[i][j]);
        }
        __syncthreads();
    }

#pragma unroll
    for (int i = 0; i < TM; i++) {
        const long row = m0 + ty * TM + i;
#pragma unroll
        for (int j = 0; j < TN; j++) {
            const int col = tx * TN + j;
            float v = acc[i][j];
            if (epi >= 1) v += bias[ncol0 + col];
            if (epi == 1) v = fmaxf(v, 0.f);
            if (addbuf != nullptr) v += addbuf[row * ldadd + ncol0 + col];
            Cb[row * ldc + col] = v;
        }
    }
}

__global__ __launch_bounds__(256) void zero2_kernel()
{
    const long n = cfg::ROWS * 128;
    long idx = (long)blockIdx.x * blockDim.x + threadIdx.x;
    if (idx < n) {
        g_sz[idx]  = 0.f;
        g_Asz[idx] = 0.f;
    }
}

__global__ __launch_bounds__(256) void soft_pack_kernel(
    const float* __restrict__ s, const float* __restrict__ alphaPtr)
{
    const long n = cfg::ROWS * 64;
    long idx = (long)blockIdx.x * blockDim.x + threadIdx.x;
    if (idx >= n) return;
    const float a = alphaPtr[0];
    const long r = idx >> 6;
    const int  c = (int)(idx & 63);
    const float v = s[idx];
    const float z = (v > a) ? (v - a) : ((v < -a) ? (v + a) : 0.f);
    g_sz[r * 128 + c]      = v;
    g_sz[r * 128 + 64 + c] = z;
}

__global__ __launch_bounds__(256) void copy_s_kernel(float* __restrict__ out)
{
    const long n = cfg::ROWS * 64;
    long idx = (long)blockIdx.x * blockDim.x + threadIdx.x;
    if (idx >= n) return;
    out[idx] = g_sz[(idx >> 6) * 128 + (idx & 63)];
}

// ============================================================================
extern "C" void kernel_launch(void* const* d_in, const int* in_sizes, int n_in,
                              void* d_out, int out_size)
{
    using namespace cfg;
    const float* x_c   = (const float*)d_in[0];
    const float* A     = (const float*)d_in[1];
    const float* alpha = (const float*)d_in[2];
    const float* WA1 = (const float*)d_in[3];
    const float* bA1 = (const float*)d_in[4];
    const float* WA2 = (const float*)d_in[5];
    const float* bA2 = (const float*)d_in[6];
    const float* WB1 = (const float*)d_in[7];
    const float* bB1 = (const float*)d_in[8];
    const float* WB2 = (const float*)d_in[9];
    const float* bB2 = (const float*)d_in[10];
    const float* WD1 = (const float*)d_in[11];
    const float* bD1 = (const float*)d_in[12];
    const float* WD2 = (const float*)d_in[13];
    const float* bD2 = (const float*)d_in[14];
    const float* WE1 = (const float*)d_in[15];
    const float* bE1 = (const float*)d_in[16];
    const float* WE2 = (const float*)d_in[17];
    const float* bE2 = (const float*)d_in[18];
    float* out = (float*)d_out;

    float *sz, *Asz, *t64, *bxp, *yp, *hid, *snew;
    __nv_bfloat16 *Ahi, *Alo, *Xhi, *Xlo;
    cudaGetSymbolAddress((void**)&sz,   g_sz);
    cudaGetSymbolAddress((void**)&Asz,  g_Asz);
    cudaGetSymbolAddress((void**)&t64,  g_t64);
    cudaGetSymbolAddress((void**)&bxp,  g_bx);
    cudaGetSymbolAddress((void**)&yp,   g_y);
    cudaGetSymbolAddress((void**)&hid,  g_hid);
    cudaGetSymbolAddress((void**)&snew, g_snew);
    cudaGetSymbolAddress((void**)&Ahi,  g_Ahi);
    cudaGetSymbolAddress((void**)&Alo,  g_Alo);
    cudaGetSymbolAddress((void**)&Xhi,  g_Xhi);
    cudaGetSymbolAddress((void**)&Xlo,  g_Xlo);

    cudaFuncSetAttribute(tgemm_hmma, cudaFuncAttributeMaxDynamicSharedMemorySize,
                         tg::SMEM_TOTAL);

    const dim3 blk(256);
    const dim3 tgb(512);
    const dim3 gT256(64, 2, 1);                 // 256 output cols
    const dim3 gT512(64, 4, 1);                 // 512 output cols
    const dim3 gM128((int)(ROWS / 128), 2, 1);
    const dim3 gM64 ((int)(ROWS / 128), 1, 1);
    const dim3 tblk(32, 8, 1);
    const dim3 gTr64 (N / 32, (BATCH * 64) / 32, 1);
    const dim3 gTr128(N / 32, (BATCH * 128) / 32, 1);

    // --- split A to bf16 hi/lo ---
    {
        const long n4 = ((long)N * N) / 4;
        split_A_kernel<<<(unsigned)((n4 + 255) / 256), blk>>>(A);
    }
    // --- init scratch ---
    {
        long n = ROWS * 128;
        zero2_kernel<<<(unsigned)((n + 255) / 256), blk>>>();
    }

    // --- t64 = A @ x_c ---
    split_transpose_kernel<<<gTr64, tblk>>>(x_c, 64);
    tgemm_hmma<<<gT256, tgb, tg::SMEM_TOTAL>>>(Ahi, Alo, Xhi, Xlo, t64, 6);
    // --- bx = mlpB(t64) ---
    sgemm64<<<gM128, blk>>>(t64, 64, 0, WB1, HID, 0, hid, HID, 0,
                            DIM, 1, bB1, nullptr, 0);
    sgemm64<<<gM64, blk>>>(hid, HID, 0, WB2, 64, 0, bxp, 64, 0,
                           HID, 2, bB2, nullptr, 0);

    for (int it = 0; it < ITERS; it++) {
        if (it > 0) {
            split_transpose_kernel<<<gTr128, tblk>>>(sz, 128);
            tgemm_hmma<<<gT512, tgb, tg::SMEM_TOTAL>>>(Ahi, Alo, Xhi, Xlo, Asz, 7);
        }
        // y = mlpA(Asz[:, 0:64]) + bx
        sgemm64<<<gM128, blk>>>(Asz, 128, 0, WA1, HID, 0, hid, HID, 0,
                                DIM, 1, bA1, nullptr, 0);
        sgemm64<<<gM64, blk>>>(hid, HID, 0, WA2, 64, 0, yp, 64, 0,
                               HID, 2, bA2, bxp, 64);
        // t64 = A @ y
        split_transpose_kernel<<<gTr64, tblk>>>(yp, 64);
        tgemm_hmma<<<gT256, tgb, tg::SMEM_TOTAL>>>(Ahi, Alo, Xhi, Xlo, t64, 6);
        // snew = mlpD(t64)
        sgemm64<<<gM128, blk>>>(t64, 64, 0, WD1, HID, 0, hid, HID, 0,
                                DIM, 1, bD1, nullptr, 0);
        sgemm64<<<gM64, blk>>>(hid, HID, 0, WD2, 64, 0, snew, 64, 0,
                               HID, 2, bD2, nullptr, 0);
        // snew += mlpE(Asz[:, 64:128])
        sgemm64<<<gM128, blk>>>(Asz + 64, 128, 0, WE1, HID, 0, hid, HID, 0,
                                DIM, 1, bE1, nullptr, 0);
        sgemm64<<<gM64, blk>>>(hid, HID, 0, WE2, 64, 0, snew, 64, 0,
                               HID, 2, bE2, snew, 64);
        {
            long n = ROWS * 64;
            soft_pack_kernel<<<(unsigned)((n + 255) / 256), blk>>>(snew, alpha);
        }
    }

    // --- out[:R*64] = mlpD(s) ; out[R*64:] = s ---
    sgemm64<<<gM128, blk>>>(sz, 128, 0, WD1, HID, 0, hid, HID, 0,
                            DIM, 1, bD1, nullptr, 0);
    sgemm64<<<gM64, blk>>>(hid, HID, 0, WD2, 64, 0, out, 64, 0,
                           HID, 2, bD2, nullptr, 0);
    {
        long n = ROWS * 64;
        copy_s_kernel<<<(unsigned)((n + 255) / 256), blk>>>(out + ROWS * 64);
    }
}

// round 5
// speedup vs baseline: 3.5752x; 1.0289x over previous
#include <cuda_runtime.h>
#include <cuda_bf16.h>
#include <cstdint>

// ============================================================================
// GUSC1 ISTA-net round 5: HMMA split-bf16 big GEMMs, now BM=64/BN=128 with
// 256 threads and 2 CTAs/SM (cross-CTA overlap to fill tensor-pipe bubbles).
// ============================================================================

namespace cfg {
constexpr int  BATCH = 4;
constexpr int  N     = 8192;
constexpr int  DIM   = 64;
constexpr int  HID   = 128;
constexpr int  ITERS = 8;
constexpr long ROWS  = (long)BATCH * N;   // 32768
}

// ---------------------------------------------------------------------------
// Scratch (device globals)
// ---------------------------------------------------------------------------
__device__ float g_sz  [cfg::BATCH * cfg::N * 128];
__device__ float g_Asz [cfg::BATCH * cfg::N * 128];
__device__ float g_t64 [cfg::BATCH * cfg::N * 64];
__device__ float g_bx  [cfg::BATCH * cfg::N * 64];
__device__ float g_y   [cfg::BATCH * cfg::N * 64];
__device__ float g_hid [cfg::BATCH * cfg::N * 128];
__device__ float g_snew[cfg::BATCH * cfg::N * 64];

__device__ __nv_bfloat16 g_Ahi[(long)cfg::N * cfg::N];
__device__ __nv_bfloat16 g_Alo[(long)cfg::N * cfg::N];
__device__ __nv_bfloat16 g_Xhi[512L * cfg::N];   // [col, K] K-major
__device__ __nv_bfloat16 g_Xlo[512L * cfg::N];

// ---------------------------------------------------------------------------
// helpers
// ---------------------------------------------------------------------------
__device__ __forceinline__ uint32_t smem_to_u32(const void* p) {
    uint32_t a;
    asm("{ .reg .u64 t; cvta.to.shared.u64 t, %1; cvt.u32.u64 %0, t; }"
        : "=r"(a) : "l"(p));
    return a;
}
__device__ __forceinline__ void cp_async16(uint32_t dst, const void* src) {
    asm volatile("cp.async.cg.shared.global [%0], [%1], 16;" :: "r"(dst), "l"(src));
}
__device__ __forceinline__ void cp_async_commit() {
    asm volatile("cp.async.commit_group;");
}
template <int NWAIT>
__device__ __forceinline__ void cp_async_wait() {
    asm volatile("cp.async.wait_group %0;" :: "n"(NWAIT));
}
__device__ __forceinline__ void ldsm_x4(uint32_t& r0, uint32_t& r1,
                                        uint32_t& r2, uint32_t& r3, uint32_t addr) {
    asm volatile("ldmatrix.sync.aligned.m8n8.x4.shared.b16 {%0,%1,%2,%3}, [%4];"
                 : "=r"(r0), "=r"(r1), "=r"(r2), "=r"(r3) : "r"(addr));
}
__device__ __forceinline__ void mma16816(float& c0, float& c1, float& c2, float& c3,
                                         uint32_t a0, uint32_t a1, uint32_t a2, uint32_t a3,
                                         uint32_t b0, uint32_t b1) {
    asm volatile("mma.sync.aligned.m16n8k16.row.col.f32.bf16.bf16.f32 "
                 "{%0,%1,%2,%3}, {%4,%5,%6,%7}, {%8,%9}, {%0,%1,%2,%3};"
                 : "+f"(c0), "+f"(c1), "+f"(c2), "+f"(c3)
                 : "r"(a0), "r"(a1), "r"(a2), "r"(a3), "r"(b0), "r"(b1));
}

// ---------------------------------------------------------------------------
// HMMA split-bf16 GEMM: out = A_fp32 @ X_fp32 (both as hi+lo bf16, 3 terms)
// BM=64, BN=128, KT=64, 256 threads, 8 warps (2x4), warp tile 32x32.
// 2 smem stages of 48KB -> 2 CTAs per SM.
// ---------------------------------------------------------------------------
namespace tg {
constexpr int K   = 8192;
constexpr int KT  = 64;
constexpr int NCH = K / KT;            // 128
constexpr int BM  = 64;
constexpr int BN  = 128;
constexpr uint32_t SZ_A = 64 * 128;    // 8192 B per A tile (hi or lo)
constexpr uint32_t SZ_B = 128 * 128;   // 16384 B per B tile
constexpr uint32_t STG  = 2 * SZ_A + 2 * SZ_B;   // 49152 B per stage
constexpr uint32_t SMEM_TOTAL = 2 * STG;         // 98304
}

// swizzled byte offset within a [row][128B] tile
__device__ __forceinline__ uint32_t swz(int row, int x) {
    return (uint32_t)(row * 128 + (x ^ ((row & 7) << 4)));
}

__global__ __launch_bounds__(256, 2) void tgemm_hmma(
    const __nv_bfloat16* __restrict__ Ahi, const __nv_bfloat16* __restrict__ Alo,
    const __nv_bfloat16* __restrict__ Bhi, const __nv_bfloat16* __restrict__ Blo,
    float* __restrict__ out, int cbShift)
{
    using namespace tg;
    extern __shared__ char smem[];
    const uint32_t sb  = smem_to_u32(smem);
    const int tid  = threadIdx.x;
    const int lane = tid & 31;
    const int wid  = tid >> 5;
    const int wm   = wid >> 2;      // 0..1
    const int wn   = wid & 3;       // 0..3
    const long m0  = (long)blockIdx.x * BM;
    const int  n0  = blockIdx.y * BN;

    // loader geometry: 16B chunks; 256 threads.
    // A tiles: 64 rows x 8 segs = 512 chunks -> rows tid>>3 and +32.
    // B tiles: 128 rows x 8 segs = 1024 chunks -> rows tid>>3, +32, +64, +96.
    const int c0r = tid >> 3;          // 0..31
    const int c0s = tid & 7;

    float acc[2][4][4];
#pragma unroll
    for (int i = 0; i < 2; i++)
#pragma unroll
        for (int j = 0; j < 4; j++)
#pragma unroll
            for (int q = 0; q < 4; q++) acc[i][j][q] = 0.f;

    // ldmatrix per-lane geometry
    const int q    = lane >> 3;        // 0..3
    const int r8   = lane & 7;
    const int a_row_off = wm * 32 + r8 + (q & 1) * 8;   // + mi*16
    const int a_k_off   = (q >> 1) * 16;                // + s*32
    const int b_row_off = wn * 32 + r8 + (q >> 1) * 8;  // + ni*16
    const int b_k_off   = (q & 1) * 16;

#define LOAD_STAGE(ST, K0)                                                     \
    do {                                                                       \
        const uint32_t base_ = sb + (uint32_t)(ST) * STG;                      \
        const uint32_t oA0_ = swz(c0r,      c0s * 16);                         \
        const uint32_t oA1_ = swz(c0r + 32, c0s * 16);                         \
        const long ga0_ = (m0 + c0r)      * (long)K + (K0) + c0s * 8;          \
        const long ga1_ = (m0 + c0r + 32) * (long)K + (K0) + c0s * 8;          \
        cp_async16(base_ + oA0_,        Ahi + ga0_);                           \
        cp_async16(base_ + oA1_,        Ahi + ga1_);                           \
        cp_async16(base_ + SZ_A + oA0_, Alo + ga0_);                           \
        cp_async16(base_ + SZ_A + oA1_, Alo + ga1_);                           \
        const uint32_t bB_ = base_ + 2 * SZ_A;                                 \
        _Pragma("unroll")                                                      \
        for (int rr_ = 0; rr_ < 4; rr_++) {                                    \
            const int brow_ = c0r + rr_ * 32;                                  \
            const uint32_t oB_ = swz(brow_, c0s * 16);                         \
            const long gb_ = ((long)n0 + brow_) * K + (K0) + c0s * 8;          \
            cp_async16(bB_ + oB_,        Bhi + gb_);                           \
            cp_async16(bB_ + SZ_B + oB_, Blo + gb_);                           \
        }                                                                      \
        cp_async_commit();                                                     \
    } while (0)

    LOAD_STAGE(0, 0);

    for (int i = 0; i < NCH; i++) {
        if (i + 1 < NCH) {
            LOAD_STAGE((i + 1) & 1, (i + 1) * KT);
            cp_async_wait<1>();
        } else {
            cp_async_wait<0>();
        }
        __syncthreads();

        const uint32_t base = sb + (uint32_t)(i & 1) * STG;
        const uint32_t aHB = base;
        const uint32_t aLB = base + SZ_A;
        const uint32_t bHB = base + 2 * SZ_A;
        const uint32_t bLB = base + 2 * SZ_A + SZ_B;

#pragma unroll
        for (int s = 0; s < 4; s++) {
            const int kb = s * 32;
            uint32_t ah[2][4], al[2][4], bh[2][4], bl[2][4];
#pragma unroll
            for (int mi = 0; mi < 2; mi++) {
                const uint32_t ad = swz(a_row_off + mi * 16, kb + a_k_off);
                ldsm_x4(ah[mi][0], ah[mi][1], ah[mi][2], ah[mi][3], aHB + ad);
                ldsm_x4(al[mi][0], al[mi][1], al[mi][2], al[mi][3], aLB + ad);
            }
#pragma unroll
            for (int ni = 0; ni < 2; ni++) {
                const uint32_t bd = swz(b_row_off + ni * 16, kb + b_k_off);
                ldsm_x4(bh[ni][0], bh[ni][1], bh[ni][2], bh[ni][3], bHB + bd);
                ldsm_x4(bl[ni][0], bl[ni][1], bl[ni][2], bl[ni][3], bLB + bd);
            }
#pragma unroll
            for (int mi = 0; mi < 2; mi++) {
#pragma unroll
                for (int nj = 0; nj < 4; nj++) {
                    const int g = nj >> 1, h = (nj & 1) * 2;
                    float* c = acc[mi][nj];
                    mma16816(c[0], c[1], c[2], c[3],
                             ah[mi][0], ah[mi][1], ah[mi][2], ah[mi][3],
                             bh[g][h], bh[g][h + 1]);
                    mma16816(c[0], c[1], c[2], c[3],
                             al[mi][0], al[mi][1], al[mi][2], al[mi][3],
                             bh[g][h], bh[g][h + 1]);
                    mma16816(c[0], c[1], c[2], c[3],
                             ah[mi][0], ah[mi][1], ah[mi][2], ah[mi][3],
                             bl[g][h], bl[g][h + 1]);
                }
            }
        }
        __syncthreads();
    }

    // ---- epilogue ----
    const int CB = 1 << cbShift;
    const int cbMask = CB - 1;
#pragma unroll
    for (int mi = 0; mi < 2; mi++) {
        const long row = m0 + wm * 32 + mi * 16 + (lane >> 2);
#pragma unroll
        for (int nj = 0; nj < 4; nj++) {
            const int g = n0 + wn * 32 + nj * 8 + 2 * (lane & 3);
            const int b = g >> cbShift;
            const int c = g & cbMask;
            float* p0 = out + ((long)b * 8192 + row) * CB + c;
            float* p1 = out + ((long)b * 8192 + row + 8) * CB + c;
            *reinterpret_cast<float2*>(p0) = make_float2(acc[mi][nj][0], acc[mi][nj][1]);
            *reinterpret_cast<float2*>(p1) = make_float2(acc[mi][nj][2], acc[mi][nj][3]);
        }
    }
#undef LOAD_STAGE
}

// ---------------------------------------------------------------------------
// A split: Ahi = bf16(a); Alo = bf16(a - Ahi)
// ---------------------------------------------------------------------------
__global__ __launch_bounds__(256) void split_A_kernel(const float* __restrict__ A)
{
    const long n = (long)cfg::N * cfg::N;
    long idx = ((long)blockIdx.x * blockDim.x + threadIdx.x) * 4;
    if (idx >= n) return;
    float4 v = *reinterpret_cast<const float4*>(A + idx);
    float f[4] = {v.x, v.y, v.z, v.w};
#pragma unroll
    for (int q = 0; q < 4; q++) {
        __nv_bfloat16 hi = __float2bfloat16(f[q]);
        g_Ahi[idx + q] = hi;
        g_Alo[idx + q] = __float2bfloat16(f[q] - __bfloat162float(hi));
    }
}

// ---------------------------------------------------------------------------
// Split + transpose X: [B*N, CB] fp32 -> Xt hi/lo [B*CB, K] bf16
// ---------------------------------------------------------------------------
__global__ __launch_bounds__(256) void split_transpose_kernel(
    const float* __restrict__ X, int CB)
{
    __shared__ float tile[32][33];
    const int k0 = blockIdx.x * 32;
    const int j0 = blockIdx.y * 32;
    const int b  = j0 / CB;
    const int c0 = j0 % CB;
    const int tx = threadIdx.x, ty = threadIdx.y;

    for (int r = ty; r < 32; r += 8)
        tile[r][tx] = X[((long)b * cfg::N + k0 + r) * CB + c0 + tx];
    __syncthreads();
    for (int r = ty; r < 32; r += 8) {
        const float v = tile[tx][r];
        const __nv_bfloat16 hi = __float2bfloat16(v);
        const long o = (long)(j0 + r) * cfg::N + k0 + tx;
        g_Xhi[o] = hi;
        g_Xlo[o] = __float2bfloat16(v - __bfloat162float(hi));
    }
}

// ----------------------------------------------------------------------------
// fp32 FFMA GEMM for the small MLPs
// ----------------------------------------------------------------------------
__global__ __launch_bounds__(256) void sgemm64(
    const float* __restrict__ Am, int lda, long strideA,
    const float* __restrict__ Bm, int ldb, long strideB,
    float*       __restrict__ Cm, int ldc, long strideC,
    int K, int epi,
    const float* __restrict__ bias,
    const float* __restrict__ addbuf, int ldadd)
{
    constexpr int BM = 128, BN = 64, BK = 8, TM = 8, TN = 4;
    __shared__ float As[BK][BM + 4];
    __shared__ float Bs[BK][BN + 4];

    const int  bz    = blockIdx.z;
    const int  ncol0 = blockIdx.y * BN;
    const float* Ab = Am + (long)bz * strideA;
    const float* Bb = Bm + (long)bz * strideB + ncol0;
    float*       Cb = Cm + (long)bz * strideC + ncol0;

    const long m0  = (long)blockIdx.x * BM;
    const int  tid = threadIdx.x;
    const int  tx  = tid & 15;
    const int  ty  = tid >> 4;

    const int arow = tid >> 1;
    const int acol = (tid & 1) * 4;
    const int brow = tid >> 5;
    const int bcol = (tid & 31) * 2;

    float acc[TM][TN];
#pragma unroll
    for (int i = 0; i < TM; i++)
#pragma unroll
        for (int j = 0; j < TN; j++) acc[i][j] = 0.f;

    for (int k0 = 0; k0 < K; k0 += BK) {
        float4 av = *reinterpret_cast<const float4*>(Ab + (m0 + arow) * lda + k0 + acol);
        As[acol + 0][arow] = av.x;
        As[acol + 1][arow] = av.y;
        As[acol + 2][arow] = av.z;
        As[acol + 3][arow] = av.w;
        float2 bv = *reinterpret_cast<const float2*>(Bb + (long)(k0 + brow) * ldb + bcol);
        Bs[brow][bcol]     = bv.x;
        Bs[brow][bcol + 1] = bv.y;
        __syncthreads();
#pragma unroll
        for (int kk = 0; kk < BK; kk++) {
            float a[TM], b[TN];
#pragma unroll
            for (int i = 0; i < TM; i++) a[i] = As[kk][ty * TM + i];
#pragma unroll
            for (int j = 0; j < TN; j++) b[j] = Bs[kk][tx * TN + j];
#pragma unroll
            for (int i = 0; i < TM; i++)
#pragma unroll
                for (int j = 0; j < TN; j++)
                    acc[i][j] = fmaf(a[i], b[j], acc[i][j]);
        }
        __syncthreads();
    }

#pragma unroll
    for (int i = 0; i < TM; i++) {
        const long row = m0 + ty * TM + i;
#pragma unroll
        for (int j = 0; j < TN; j++) {
            const int col = tx * TN + j;
            float v = acc[i][j];
            if (epi >= 1) v += bias[ncol0 + col];
            if (epi == 1) v = fmaxf(v, 0.f);
            if (addbuf != nullptr) v += addbuf[row * ldadd + ncol0 + col];
            Cb[row * ldc + col] = v;
        }
    }
}

__global__ __launch_bounds__(256) void zero2_kernel()
{
    const long n = cfg::ROWS * 128;
    long idx = (long)blockIdx.x * blockDim.x + threadIdx.x;
    if (idx < n) {
        g_sz[idx]  = 0.f;
        g_Asz[idx] = 0.f;
    }
}

__global__ __launch_bounds__(256) void soft_pack_kernel(
    const float* __restrict__ s, const float* __restrict__ alphaPtr)
{
    const long n = cfg::ROWS * 64;
    long idx = (long)blockIdx.x * blockDim.x + threadIdx.x;
    if (idx >= n) return;
    const float a = alphaPtr[0];
    const long r = idx >> 6;
    const int  c = (int)(idx & 63);
    const float v = s[idx];
    const float z = (v > a) ? (v - a) : ((v < -a) ? (v + a) : 0.f);
    g_sz[r * 128 + c]      = v;
    g_sz[r * 128 + 64 + c] = z;
}

__global__ __launch_bounds__(256) void copy_s_kernel(float* __restrict__ out)
{
    const long n = cfg::ROWS * 64;
    long idx = (long)blockIdx.x * blockDim.x + threadIdx.x;
    if (idx >= n) return;
    out[idx] = g_sz[(idx >> 6) * 128 + (idx & 63)];
}

// ============================================================================
extern "C" void kernel_launch(void* const* d_in, const int* in_sizes, int n_in,
                              void* d_out, int out_size)
{
    using namespace cfg;
    const float* x_c   = (const float*)d_in[0];
    const float* A     = (const float*)d_in[1];
    const float* alpha = (const float*)d_in[2];
    const float* WA1 = (const float*)d_in[3];
    const float* bA1 = (const float*)d_in[4];
    const float* WA2 = (const float*)d_in[5];
    const float* bA2 = (const float*)d_in[6];
    const float* WB1 = (const float*)d_in[7];
    const float* bB1 = (const float*)d_in[8];
    const float* WB2 = (const float*)d_in[9];
    const float* bB2 = (const float*)d_in[10];
    const float* WD1 = (const float*)d_in[11];
    const float* bD1 = (const float*)d_in[12];
    const float* WD2 = (const float*)d_in[13];
    const float* bD2 = (const float*)d_in[14];
    const float* WE1 = (const float*)d_in[15];
    const float* bE1 = (const float*)d_in[16];
    const float* WE2 = (const float*)d_in[17];
    const float* bE2 = (const float*)d_in[18];
    float* out = (float*)d_out;

    float *sz, *Asz, *t64, *bxp, *yp, *hid, *snew;
    __nv_bfloat16 *Ahi, *Alo, *Xhi, *Xlo;
    cudaGetSymbolAddress((void**)&sz,   g_sz);
    cudaGetSymbolAddress((void**)&Asz,  g_Asz);
    cudaGetSymbolAddress((void**)&t64,  g_t64);
    cudaGetSymbolAddress((void**)&bxp,  g_bx);
    cudaGetSymbolAddress((void**)&yp,   g_y);
    cudaGetSymbolAddress((void**)&hid,  g_hid);
    cudaGetSymbolAddress((void**)&snew, g_snew);
    cudaGetSymbolAddress((void**)&Ahi,  g_Ahi);
    cudaGetSymbolAddress((void**)&Alo,  g_Alo);
    cudaGetSymbolAddress((void**)&Xhi,  g_Xhi);
    cudaGetSymbolAddress((void**)&Xlo,  g_Xlo);

    cudaFuncSetAttribute(tgemm_hmma, cudaFuncAttributeMaxDynamicSharedMemorySize,
                         tg::SMEM_TOTAL);

    const dim3 blk(256);
    const dim3 tgb(256);
    const dim3 gT256(128, 2, 1);                // 256 output cols
    const dim3 gT512(128, 4, 1);                // 512 output cols
    const dim3 gM128((int)(ROWS / 128), 2, 1);
    const dim3 gM64 ((int)(ROWS / 128), 1, 1);
    const dim3 tblk(32, 8, 1);
    const dim3 gTr64 (N / 32, (BATCH * 64) / 32, 1);
    const dim3 gTr128(N / 32, (BATCH * 128) / 32, 1);

    // --- split A to bf16 hi/lo ---
    {
        const long n4 = ((long)N * N) / 4;
        split_A_kernel<<<(unsigned)((n4 + 255) / 256), blk>>>(A);
    }
    // --- init scratch ---
    {
        long n = ROWS * 128;
        zero2_kernel<<<(unsigned)((n + 255) / 256), blk>>>();
    }

    // --- t64 = A @ x_c ---
    split_transpose_kernel<<<gTr64, tblk>>>(x_c, 64);
    tgemm_hmma<<<gT256, tgb, tg::SMEM_TOTAL>>>(Ahi, Alo, Xhi, Xlo, t64, 6);
    // --- bx = mlpB(t64) ---
    sgemm64<<<gM128, blk>>>(t64, 64, 0, WB1, HID, 0, hid, HID, 0,
                            DIM, 1, bB1, nullptr, 0);
    sgemm64<<<gM64, blk>>>(hid, HID, 0, WB2, 64, 0, bxp, 64, 0,
                           HID, 2, bB2, nullptr, 0);

    for (int it = 0; it < ITERS; it++) {
        if (it > 0) {
            split_transpose_kernel<<<gTr128, tblk>>>(sz, 128);
            tgemm_hmma<<<gT512, tgb, tg::SMEM_TOTAL>>>(Ahi, Alo, Xhi, Xlo, Asz, 7);
        }
        // y = mlpA(Asz[:, 0:64]) + bx
        sgemm64<<<gM128, blk>>>(Asz, 128, 0, WA1, HID, 0, hid, HID, 0,
                                DIM, 1, bA1, nullptr, 0);
        sgemm64<<<gM64, blk>>>(hid, HID, 0, WA2, 64, 0, yp, 64, 0,
                               HID, 2, bA2, bxp, 64);
        // t64 = A @ y
        split_transpose_kernel<<<gTr64, tblk>>>(yp, 64);
        tgemm_hmma<<<gT256, tgb, tg::SMEM_TOTAL>>>(Ahi, Alo, Xhi, Xlo, t64, 6);
        // snew = mlpD(t64)
        sgemm64<<<gM128, blk>>>(t64, 64, 0, WD1, HID, 0, hid, HID, 0,
                                DIM, 1, bD1, nullptr, 0);
        sgemm64<<<gM64, blk>>>(hid, HID, 0, WD2, 64, 0, snew, 64, 0,
                               HID, 2, bD2, nullptr, 0);
        // snew += mlpE(Asz[:, 64:128])
        sgemm64<<<gM128, blk>>>(Asz + 64, 128, 0, WE1, HID, 0, hid, HID, 0,
                                DIM, 1, bE1, nullptr, 0);
        sgemm64<<<gM64, blk>>>(hid, HID, 0, WE2, 64, 0, snew, 64, 0,
                               HID, 2, bE2, snew, 64);
        {
            long n = ROWS * 64;
            soft_pack_kernel<<<(unsigned)((n + 255) / 256), blk>>>(snew, alpha);
        }
    }

    // --- out[:R*64] = mlpD(s) ; out[R*64:] = s ---
    sgemm64<<<gM128, blk>>>(sz, 128, 0, WD1, HID, 0, hid, HID, 0,
                            DIM, 1, bD1, nullptr, 0);
    sgemm64<<<gM64, blk>>>(hid, HID, 0, WD2, 64, 0, out, 64, 0,
                           HID, 2, bD2, nullptr, 0);
    {
        long n = ROWS * 64;
        copy_s_kernel<<<(unsigned)((n + 255) / 256), blk>>>(out + ROWS * 64);
    }
}